// round 5
// baseline (speedup 1.0000x reference)
#include <cuda_runtime.h>
#include <cuda_fp16.h>

#define N_NODES 100000
#define N_EDGES 500000
#define IN_DIM 16
#define HEADS 4
#define OUT_DIM 128
#define HC 512           // HEADS*OUT_DIM
#define NEG 0.2f

// Scratch (device globals: allocation-free per harness rules)
__device__ __half g_xl[(size_t)N_NODES * HC];    // 102.4 MB
__device__ __half g_xr[(size_t)N_NODES * HC];    // 102.4 MB
__device__ int    g_counts[N_NODES];
__device__ int    g_row[N_NODES + 1];
__device__ int    g_cursor[N_NODES];
__device__ int    g_srcs[N_EDGES];               // CSR: src per slot

__device__ __forceinline__ float lrelu(float v) { return v > 0.f ? v : NEG * v; }

// packed f32x2 helpers (sm_103a; ptxas never auto-fuses these)
__device__ __forceinline__ unsigned long long pack2(float lo, float hi) {
    unsigned long long r;
    asm("mov.b64 %0, {%1, %2};" : "=l"(r) : "f"(lo), "f"(hi));
    return r;
}
__device__ __forceinline__ void unpack2(unsigned long long v, float& lo, float& hi) {
    asm("mov.b64 {%0, %1}, %2;" : "=f"(lo), "=f"(hi) : "l"(v));
}
__device__ __forceinline__ void ffma2(unsigned long long& d,
                                      unsigned long long a, unsigned long long b) {
    asm("fma.rn.f32x2 %0, %1, %2, %3;" : "=l"(d) : "l"(a), "l"(b), "l"(d));
}

// ---------------------------------------------------------------------------
// K1: x_l = X@W_l + b_l ; x_r = X@W_r + b_r, fp16 out, packed f32x2 FMA.
// X pre-packed (replicated) into u64 smem ONCE, so the inner loop is pure FMA2.
// Thread owns 2 adjacent columns; 128 nodes per 256-thread block.
// ---------------------------------------------------------------------------
__global__ __launch_bounds__(256) void proj_kernel(
    const float* __restrict__ X,
    const float* __restrict__ Wl, const float* __restrict__ bl,
    const float* __restrict__ Wr, const float* __restrict__ br)
{
    __shared__ unsigned long long sx2[128 * IN_DIM];  // 16 KB
    const int c0 = threadIdx.x * 2;
    unsigned long long wl[IN_DIM], wr[IN_DIM];
#pragma unroll
    for (int k = 0; k < IN_DIM; k++) {
        wl[k] = pack2(Wl[k * HC + c0], Wl[k * HC + c0 + 1]);
        wr[k] = pack2(Wr[k * HC + c0], Wr[k * HC + c0 + 1]);
    }
    const unsigned long long bl2 = pack2(bl[c0], bl[c0 + 1]);
    const unsigned long long br2 = pack2(br[c0], br[c0 + 1]);

    const int n0 = blockIdx.x * 128;
    const int nmax = min(128, N_NODES - n0);

    for (int i = threadIdx.x; i < nmax * IN_DIM; i += blockDim.x) {
        const float v = X[(size_t)n0 * IN_DIM + i];
        sx2[i] = pack2(v, v);
    }
    __syncthreads();

    for (int n = 0; n < nmax; n++) {
        unsigned long long al = bl2, ar = br2;
#pragma unroll
        for (int k = 0; k < IN_DIM; k++) {
            const unsigned long long x2 = sx2[n * IN_DIM + k];
            ffma2(al, x2, wl[k]);
            ffma2(ar, x2, wr[k]);
        }
        float l0, l1, r0, r1;
        unpack2(al, l0, l1);
        unpack2(ar, r0, r1);
        const size_t o = ((size_t)(n0 + n) * HC + c0) >> 1;
        ((__half2*)g_xl)[o] = __floats2half2_rn(l0, l1);
        ((__half2*)g_xr)[o] = __floats2half2_rn(r0, r1);
    }
}

// ---------------------------------------------------------------------------
// CSR build: histogram -> single-block scan -> fill
// ---------------------------------------------------------------------------
__global__ __launch_bounds__(256) void hist_kernel(const int* __restrict__ idx)
{
    const int e = blockIdx.x * blockDim.x + threadIdx.x;
    if (e < N_EDGES) atomicAdd(&g_counts[idx[N_EDGES + e]], 1);
}

__global__ __launch_bounds__(1024) void scan_kernel()
{
    __shared__ int sp[1024];
    const int t = threadIdx.x;
    const int CH = (N_NODES + 1023) / 1024;
    const int base = t * CH;
    const int lim = min(CH, N_NODES - base);

    int sum = 0;
    for (int i = 0; i < lim; i++) sum += g_counts[base + i];
    sp[t] = sum;
    __syncthreads();
    for (int off = 1; off < 1024; off <<= 1) {
        int v = (t >= off) ? sp[t - off] : 0;
        __syncthreads();
        sp[t] += v;
        __syncthreads();
    }
    int run = (t > 0) ? sp[t - 1] : 0;
    for (int i = 0; i < lim; i++) {
        g_row[base + i] = run;
        g_cursor[base + i] = run;
        run += g_counts[base + i];
    }
    if (t == 0) g_row[N_NODES] = N_EDGES;
}

__global__ __launch_bounds__(256) void fill_kernel(const int* __restrict__ idx)
{
    const int e = blockIdx.x * blockDim.x + threadIdx.x;
    if (e >= N_EDGES) return;
    const int dst = idx[N_EDGES + e];
    const int pos = atomicAdd(&g_cursor[dst], 1);
    g_srcs[pos] = idx[e];
}

// ---------------------------------------------------------------------------
// K2 (fully fused): one warp per dst node.
//   x_r row read ONCE into registers; srcs preloaded lane-parallel (no
//   dependent uniform loads); per edge: gather x_l[src] (fp16), score via
//   butterfly reduce (sum lands in all lanes -> everyone does expf + FMA),
//   accumulate numerator/denominator in registers; single coalesced write
//   with 1/den and bias fused. One pass over x_l; no atomics; no scratch ex.
// No max-subtraction: scores are O(1), exp safe in fp32, softmax ratio exact.
// ---------------------------------------------------------------------------
__global__ __launch_bounds__(256) void fused_kernel(
    const float* __restrict__ att, const float* __restrict__ bias,
    float* __restrict__ out)
{
    const int node = blockIdx.x * 8 + (threadIdx.x >> 5);
    if (node >= N_NODES) return;
    const int lane = threadIdx.x & 31;
    const unsigned FULL = 0xffffffffu;

    // x_r[node] for this lane's 4 columns per head
    float4 xr[HEADS];
    {
        const uint2* __restrict__ xrp = ((const uint2*)g_xr) + (size_t)node * 128;
#pragma unroll
        for (int h = 0; h < HEADS; h++) {
            const uint2 p = xrp[h * 32 + lane];
            const float2 f0 = __half22float2(*(const __half2*)&p.x);
            const float2 f1 = __half22float2(*(const __half2*)&p.y);
            xr[h] = make_float4(f0.x, f0.y, f1.x, f1.y);
        }
    }

    float4 aw[HEADS];
#pragma unroll
    for (int h = 0; h < HEADS; h++)
        aw[h] = __ldg(&((const float4*)att)[h * 32 + lane]);

    float4 acc[HEADS];
#pragma unroll
    for (int h = 0; h < HEADS; h++) acc[h] = make_float4(0.f, 0.f, 0.f, 0.f);
    float den[HEADS] = {0.f, 0.f, 0.f, 0.f};

    const int eb = g_row[node];
    const int ee = g_row[node + 1];

    for (int b = eb; b < ee; b += 32) {
        const int cnt = min(32, ee - b);
        int li = b + lane;
        if (li >= ee) li = eb;               // safe clamp
        const int my_src = g_srcs[li];       // lane-parallel preload

        for (int j = 0; j < cnt; j++) {
            const int src = __shfl_sync(FULL, my_src, j);
            const uint2* __restrict__ xlp = ((const uint2*)g_xl) + (size_t)src * 128;

            uint2 p[HEADS];
#pragma unroll
            for (int h = 0; h < HEADS; h++) p[h] = xlp[h * 32 + lane];

            float xf[HEADS][4];
            float eh[HEADS];
#pragma unroll
            for (int h = 0; h < HEADS; h++) {
                const float2 f0 = __half22float2(*(const __half2*)&p[h].x);
                const float2 f1 = __half22float2(*(const __half2*)&p[h].y);
                xf[h][0] = f0.x; xf[h][1] = f0.y; xf[h][2] = f1.x; xf[h][3] = f1.y;
                float s = lrelu(f0.x + xr[h].x) * aw[h].x;
                s = fmaf(lrelu(f0.y + xr[h].y), aw[h].y, s);
                s = fmaf(lrelu(f1.x + xr[h].z), aw[h].z, s);
                s = fmaf(lrelu(f1.y + xr[h].w), aw[h].w, s);
                eh[h] = s;
            }
            // butterfly: full sum lands in every lane (4 independent trees)
#pragma unroll
            for (int off = 16; off > 0; off >>= 1) {
#pragma unroll
                for (int h = 0; h < HEADS; h++)
                    eh[h] += __shfl_xor_sync(FULL, eh[h], off);
            }
#pragma unroll
            for (int h = 0; h < HEADS; h++) {
                const float ex = __expf(eh[h]);
                acc[h].x = fmaf(ex, xf[h][0], acc[h].x);
                acc[h].y = fmaf(ex, xf[h][1], acc[h].y);
                acc[h].z = fmaf(ex, xf[h][2], acc[h].z);
                acc[h].w = fmaf(ex, xf[h][3], acc[h].w);
                den[h] += ex;
            }
        }
    }

    float4* op = ((float4*)out) + (size_t)node * (HC / 4);
#pragma unroll
    for (int h = 0; h < HEADS; h++) {
        const float inv = (den[h] > 0.f) ? (1.0f / den[h]) : 0.f;
        const float4 bst = __ldg(&((const float4*)bias)[h * 32 + lane]);
        float4 o;
        o.x = fmaf(acc[h].x, inv, bst.x);
        o.y = fmaf(acc[h].y, inv, bst.y);
        o.z = fmaf(acc[h].z, inv, bst.z);
        o.w = fmaf(acc[h].w, inv, bst.w);
        op[h * 32 + lane] = o;
    }
}

// ---------------------------------------------------------------------------
extern "C" void kernel_launch(void* const* d_in, const int* in_sizes, int n_in,
                              void* d_out, int out_size)
{
    const float* X    = (const float*)d_in[0];  // [N, 16]
    const int*   idx  = (const int*)  d_in[1];  // [2, E]
    const float* Wl   = (const float*)d_in[2];  // [16, 512]
    const float* bl   = (const float*)d_in[3];  // [512]
    const float* Wr   = (const float*)d_in[4];  // [16, 512]
    const float* br   = (const float*)d_in[5];  // [512]
    const float* att  = (const float*)d_in[6];  // [4, 128]
    const float* bias = (const float*)d_in[7];  // [512]
    float* out = (float*)d_out;                 // [N, 512]

    void* counts_ptr = nullptr;
    cudaGetSymbolAddress(&counts_ptr, g_counts);
    cudaMemsetAsync(counts_ptr, 0, N_NODES * sizeof(int), 0);

    proj_kernel<<<(N_NODES + 127) / 128, 256>>>(X, Wl, bl, Wr, br);
    hist_kernel<<<(N_EDGES + 255) / 256, 256>>>(idx);
    scan_kernel<<<1, 1024>>>();
    fill_kernel<<<(N_EDGES + 255) / 256, 256>>>(idx);
    fused_kernel<<<(N_NODES + 7) / 8, 256>>>(att, bias, out);
}

// round 6
// speedup vs baseline: 1.1027x; 1.1027x over previous
#include <cuda_runtime.h>
#include <cuda_fp16.h>

#define N_NODES 100000
#define N_EDGES 500000
#define IN_DIM 16
#define HEADS 4
#define OUT_DIM 128
#define HC 512           // HEADS*OUT_DIM
#define NEG 0.2f

// Scratch (device globals: allocation-free per harness rules)
__device__ __half g_xl[(size_t)N_NODES * HC];    // 102.4 MB
__device__ __half g_xr[(size_t)N_NODES * HC];    // 102.4 MB
__device__ float  g_ex[(size_t)N_EDGES * HEADS]; // 8 MB, CSR slot order
__device__ int    g_counts[N_NODES];
__device__ int    g_row[N_NODES + 1];
__device__ int    g_cursor[N_NODES];
__device__ int    g_srcs[N_EDGES];               // CSR: src per slot
__device__ int    g_dsts[N_EDGES];               // CSR: dst per slot

__device__ __forceinline__ float lrelu(float v) { return v > 0.f ? v : NEG * v; }

// packed f32x2 helpers (sm_103a; ptxas never auto-fuses these)
__device__ __forceinline__ unsigned long long pack2(float lo, float hi) {
    unsigned long long r;
    asm("mov.b64 %0, {%1, %2};" : "=l"(r) : "f"(lo), "f"(hi));
    return r;
}
__device__ __forceinline__ void unpack2(unsigned long long v, float& lo, float& hi) {
    asm("mov.b64 {%0, %1}, %2;" : "=f"(lo), "=f"(hi) : "l"(v));
}
__device__ __forceinline__ void ffma2(unsigned long long& d,
                                      unsigned long long a, unsigned long long b) {
    asm("fma.rn.f32x2 %0, %1, %2, %3;" : "=l"(d) : "l"(a), "l"(b), "l"(d));
}

// ---------------------------------------------------------------------------
// K1: x_l = X@W_l + b_l ; x_r = X@W_r + b_r, fp16 out, packed f32x2 FMA.
// ---------------------------------------------------------------------------
__global__ __launch_bounds__(256) void proj_kernel(
    const float* __restrict__ X,
    const float* __restrict__ Wl, const float* __restrict__ bl,
    const float* __restrict__ Wr, const float* __restrict__ br)
{
    __shared__ unsigned long long sx2[128 * IN_DIM];  // 16 KB
    const int c0 = threadIdx.x * 2;
    unsigned long long wl[IN_DIM], wr[IN_DIM];
#pragma unroll
    for (int k = 0; k < IN_DIM; k++) {
        wl[k] = pack2(Wl[k * HC + c0], Wl[k * HC + c0 + 1]);
        wr[k] = pack2(Wr[k * HC + c0], Wr[k * HC + c0 + 1]);
    }
    const unsigned long long bl2 = pack2(bl[c0], bl[c0 + 1]);
    const unsigned long long br2 = pack2(br[c0], br[c0 + 1]);

    const int n0 = blockIdx.x * 128;
    const int nmax = min(128, N_NODES - n0);

    for (int i = threadIdx.x; i < nmax * IN_DIM; i += blockDim.x) {
        const float v = X[(size_t)n0 * IN_DIM + i];
        sx2[i] = pack2(v, v);
    }
    __syncthreads();

    for (int n = 0; n < nmax; n++) {
        unsigned long long al = bl2, ar = br2;
#pragma unroll
        for (int k = 0; k < IN_DIM; k++) {
            const unsigned long long x2 = sx2[n * IN_DIM + k];
            ffma2(al, x2, wl[k]);
            ffma2(ar, x2, wr[k]);
        }
        float l0, l1, r0, r1;
        unpack2(al, l0, l1);
        unpack2(ar, r0, r1);
        const size_t o = ((size_t)(n0 + n) * HC + c0) >> 1;
        ((__half2*)g_xl)[o] = __floats2half2_rn(l0, l1);
        ((__half2*)g_xr)[o] = __floats2half2_rn(r0, r1);
    }
}

// ---------------------------------------------------------------------------
// CSR build: histogram -> single-block scan -> fill
// ---------------------------------------------------------------------------
__global__ __launch_bounds__(256) void hist_kernel(const int* __restrict__ idx)
{
    const int e = blockIdx.x * blockDim.x + threadIdx.x;
    if (e < N_EDGES) atomicAdd(&g_counts[idx[N_EDGES + e]], 1);
}

__global__ __launch_bounds__(1024) void scan_kernel()
{
    __shared__ int sp[1024];
    const int t = threadIdx.x;
    const int CH = (N_NODES + 1023) / 1024;
    const int base = t * CH;
    const int lim = min(CH, N_NODES - base);

    int sum = 0;
    for (int i = 0; i < lim; i++) sum += g_counts[base + i];
    sp[t] = sum;
    __syncthreads();
    for (int off = 1; off < 1024; off <<= 1) {
        int v = (t >= off) ? sp[t - off] : 0;
        __syncthreads();
        sp[t] += v;
        __syncthreads();
    }
    int run = (t > 0) ? sp[t - 1] : 0;
    for (int i = 0; i < lim; i++) {
        g_row[base + i] = run;
        g_cursor[base + i] = run;
        run += g_counts[base + i];
    }
    if (t == 0) g_row[N_NODES] = N_EDGES;
}

__global__ __launch_bounds__(256) void fill_kernel(const int* __restrict__ idx)
{
    const int e = blockIdx.x * blockDim.x + threadIdx.x;
    if (e >= N_EDGES) return;
    const int dst = idx[N_EDGES + e];
    const int pos = atomicAdd(&g_cursor[dst], 1);
    g_srcs[pos] = idx[e];
    g_dsts[pos] = dst;
}

// ---------------------------------------------------------------------------
// K2: edge-centric scores, CSR order (consecutive slots share dst -> x_r
// L1/L2 reuse). One warp per slot. uint4 loads: lane covers 8 cols, warp
// load covers 2 heads (lanes 0-15 = head 2g, 16-31 = head 2g+1). Head sums
// reduce over 16 lanes: 8 butterfly shuffles total (vs 20 in the uint2
// version). No max-subtraction: scores are O(1), softmax ratio exact.
// ---------------------------------------------------------------------------
__global__ __launch_bounds__(256) void score_kernel(const float* __restrict__ att)
{
    const int j = blockIdx.x * 8 + (threadIdx.x >> 5);
    if (j >= N_EDGES) return;
    const int lane = threadIdx.x & 31;
    const unsigned FULL = 0xffffffffu;
    const int src = g_srcs[j];
    const int dst = g_dsts[j];

    const uint4* __restrict__ xlp = ((const uint4*)g_xl) + (size_t)src * 64;
    const uint4* __restrict__ xrp = ((const uint4*)g_xr) + (size_t)dst * 64;

    float s[2];
#pragma unroll
    for (int g = 0; g < 2; g++) {
        const uint4 a = xlp[g * 32 + lane];
        const uint4 b = xrp[g * 32 + lane];
        // attention row for this lane's head & 8 columns
        const int hh = 2 * g + (lane >> 4);
        const float* attrow = att + hh * OUT_DIM + (lane & 15) * 8;
        const float4 w0 = __ldg((const float4*)attrow);
        const float4 w1 = __ldg((const float4*)(attrow + 4));

        const unsigned int au[4] = {a.x, a.y, a.z, a.w};
        const unsigned int bu[4] = {b.x, b.y, b.z, b.w};
        float acc = 0.f;
#pragma unroll
        for (int i = 0; i < 4; i++) {
            const float2 fa = __half22float2(*(const __half2*)&au[i]);
            const float2 fb = __half22float2(*(const __half2*)&bu[i]);
            const float wa = (i == 0) ? w0.x : (i == 1) ? w0.z : (i == 2) ? w1.x : w1.z;
            const float wb = (i == 0) ? w0.y : (i == 1) ? w0.w : (i == 2) ? w1.y : w1.w;
            acc = fmaf(lrelu(fa.x + fb.x), wa, acc);
            acc = fmaf(lrelu(fa.y + fb.y), wb, acc);
        }
        s[g] = acc;
    }
    // reduce within 16-lane halves (xor offsets < 16 stay inside the half)
#pragma unroll
    for (int off = 8; off > 0; off >>= 1) {
        s[0] += __shfl_xor_sync(FULL, s[0], off);
        s[1] += __shfl_xor_sync(FULL, s[1], off);
    }
    const float ex0 = __expf(s[0]);   // lanes 0-15: head0 ; 16-31: head1
    const float ex1 = __expf(s[1]);   // lanes 0-15: head2 ; 16-31: head3
    const float e1 = __shfl_xor_sync(FULL, ex0, 16);
    const float e3 = __shfl_xor_sync(FULL, ex1, 16);
    if (lane == 0)
        ((float4*)g_ex)[j] = make_float4(ex0, e1, ex1, e3);
}

// ---------------------------------------------------------------------------
// K3: node-centric aggregate. One warp per node. srcs preloaded lane-parallel
// (shfl broadcast, no dependent uniform loads); per edge 2 uint4 gathers;
// ex float4 is a sequential L1-resident uniform load. Single coalesced write
// with 1/den and bias fused. No atomics, no out-memset, no finalize.
// ---------------------------------------------------------------------------
__global__ __launch_bounds__(256) void aggregate_kernel(
    const float* __restrict__ bias, float* __restrict__ out)
{
    const int node = blockIdx.x * 8 + (threadIdx.x >> 5);
    if (node >= N_NODES) return;
    const int lane = threadIdx.x & 31;
    const unsigned FULL = 0xffffffffu;
    const int hi16 = lane >> 4;

    const int eb = g_row[node];
    const int ee = g_row[node + 1];

    float acc[2][8];
#pragma unroll
    for (int g = 0; g < 2; g++)
#pragma unroll
        for (int k = 0; k < 8; k++) acc[g][k] = 0.f;
    float den0 = 0.f, den1 = 0.f;

    for (int b = eb; b < ee; b += 32) {
        const int cnt = min(32, ee - b);
        int li = b + lane;
        if (li >= ee) li = eb;               // safe clamp
        const int my_src = g_srcs[li];       // lane-parallel preload

        for (int j2 = 0; j2 < cnt; j2++) {
            const int src = __shfl_sync(FULL, my_src, j2);
            const float4 ex = __ldg(((const float4*)g_ex) + (b + j2));
            const float w0 = hi16 ? ex.y : ex.x;   // group0 head weight
            const float w1 = hi16 ? ex.w : ex.z;   // group1 head weight
            const uint4* __restrict__ xlp = ((const uint4*)g_xl) + (size_t)src * 64;

            const uint4 a0 = xlp[lane];
            const uint4 a1 = xlp[32 + lane];
            const unsigned int u0[4] = {a0.x, a0.y, a0.z, a0.w};
            const unsigned int u1[4] = {a1.x, a1.y, a1.z, a1.w};
#pragma unroll
            for (int i = 0; i < 4; i++) {
                const float2 f0 = __half22float2(*(const __half2*)&u0[i]);
                const float2 f1 = __half22float2(*(const __half2*)&u1[i]);
                acc[0][2 * i]     = fmaf(w0, f0.x, acc[0][2 * i]);
                acc[0][2 * i + 1] = fmaf(w0, f0.y, acc[0][2 * i + 1]);
                acc[1][2 * i]     = fmaf(w1, f1.x, acc[1][2 * i]);
                acc[1][2 * i + 1] = fmaf(w1, f1.y, acc[1][2 * i + 1]);
            }
            den0 += w0;
            den1 += w1;
        }
    }

    const float inv0 = (den0 > 0.f) ? (1.0f / den0) : 0.f;
    const float inv1 = (den1 > 0.f) ? (1.0f / den1) : 0.f;

    float* op = out + (size_t)node * HC;
#pragma unroll
    for (int g = 0; g < 2; g++) {
        const int hh = 2 * g + hi16;
        const int off = hh * OUT_DIM + (lane & 15) * 8;
        const float inv = g ? inv1 : inv0;
        const float4 b0 = __ldg((const float4*)(bias + off));
        const float4 b1 = __ldg((const float4*)(bias + off + 4));
        float4 o0, o1;
        o0.x = fmaf(acc[g][0], inv, b0.x);
        o0.y = fmaf(acc[g][1], inv, b0.y);
        o0.z = fmaf(acc[g][2], inv, b0.z);
        o0.w = fmaf(acc[g][3], inv, b0.w);
        o1.x = fmaf(acc[g][4], inv, b1.x);
        o1.y = fmaf(acc[g][5], inv, b1.y);
        o1.z = fmaf(acc[g][6], inv, b1.z);
        o1.w = fmaf(acc[g][7], inv, b1.w);
        *(float4*)(op + off) = o0;
        *(float4*)(op + off + 4) = o1;
    }
}

// ---------------------------------------------------------------------------
extern "C" void kernel_launch(void* const* d_in, const int* in_sizes, int n_in,
                              void* d_out, int out_size)
{
    const float* X    = (const float*)d_in[0];  // [N, 16]
    const int*   idx  = (const int*)  d_in[1];  // [2, E]
    const float* Wl   = (const float*)d_in[2];  // [16, 512]
    const float* bl   = (const float*)d_in[3];  // [512]
    const float* Wr   = (const float*)d_in[4];  // [16, 512]
    const float* br   = (const float*)d_in[5];  // [512]
    const float* att  = (const float*)d_in[6];  // [4, 128]
    const float* bias = (const float*)d_in[7];  // [512]
    float* out = (float*)d_out;                 // [N, 512]

    void* counts_ptr = nullptr;
    cudaGetSymbolAddress(&counts_ptr, g_counts);
    cudaMemsetAsync(counts_ptr, 0, N_NODES * sizeof(int), 0);

    proj_kernel<<<(N_NODES + 127) / 128, 256>>>(X, Wl, bl, Wr, br);
    hist_kernel<<<(N_EDGES + 255) / 256, 256>>>(idx);
    scan_kernel<<<1, 1024>>>();
    fill_kernel<<<(N_EDGES + 255) / 256, 256>>>(idx);
    score_kernel<<<(N_EDGES + 7) / 8, 256>>>(att);
    aggregate_kernel<<<(N_NODES + 7) / 8, 256>>>(bias, out);
}

// round 8
// speedup vs baseline: 1.1401x; 1.0339x over previous
#include <cuda_runtime.h>
#include <cuda_fp16.h>

#define N_NODES 100000
#define N_EDGES 500000
#define IN_DIM 16
#define HEADS 4
#define OUT_DIM 128
#define HC 512           // HEADS*OUT_DIM
#define NEG 0.2f

// Scratch (device globals: allocation-free per harness rules)
__device__ __half g_xl[(size_t)N_NODES * HC];    // 102.4 MB
__device__ __half g_xr[(size_t)N_NODES * HC];    // 102.4 MB
__device__ float  g_ex[(size_t)N_EDGES * HEADS]; // 8 MB, CSR slot order
__device__ int    g_counts[N_NODES];
__device__ int    g_row[N_NODES + 1];
__device__ int    g_cursor[N_NODES];
__device__ int    g_srcs[N_EDGES];               // CSR: src per slot
__device__ int    g_dsts[N_EDGES];               // CSR: dst per slot

__device__ __forceinline__ float lrelu(float v) { return v > 0.f ? v : NEG * v; }

// packed f32x2 helpers (sm_103a; ptxas never auto-fuses these)
__device__ __forceinline__ unsigned long long pack2(float lo, float hi) {
    unsigned long long r;
    asm("mov.b64 %0, {%1, %2};" : "=l"(r) : "f"(lo), "f"(hi));
    return r;
}
__device__ __forceinline__ void unpack2(unsigned long long v, float& lo, float& hi) {
    asm("mov.b64 {%0, %1}, %2;" : "=f"(lo), "=f"(hi) : "l"(v));
}
__device__ __forceinline__ void ffma2(unsigned long long& d,
                                      unsigned long long a, unsigned long long b) {
    asm("fma.rn.f32x2 %0, %1, %2, %3;" : "=l"(d) : "l"(a), "l"(b), "l"(d));
}

// cache-steered loads via createpolicy + L2::cache_hint (width-agnostic form;
// the bare .L2::evict_last qualifier requires 256-bit loads on this ptxas).
__device__ __forceinline__ unsigned long long policy_evict_last() {
    unsigned long long p;
    asm("createpolicy.fractional.L2::evict_last.b64 %0, 1.0;" : "=l"(p));
    return p;
}
__device__ __forceinline__ unsigned long long policy_evict_first() {
    unsigned long long p;
    asm("createpolicy.fractional.L2::evict_first.b64 %0, 1.0;" : "=l"(p));
    return p;
}
__device__ __forceinline__ uint2 ld_hint_u2(const uint2* p, unsigned long long pol) {
    uint2 v;
    asm("ld.global.nc.L2::cache_hint.v2.u32 {%0, %1}, [%2], %3;"
        : "=r"(v.x), "=r"(v.y) : "l"(p), "l"(pol));
    return v;
}
__device__ __forceinline__ void st_stream_f4(float4* p, float4 v) {
    asm volatile("st.global.cs.v4.f32 [%0], {%1, %2, %3, %4};"
                 :: "l"(p), "f"(v.x), "f"(v.y), "f"(v.z), "f"(v.w) : "memory");
}

// ---------------------------------------------------------------------------
// K1: x_l = X@W_l + b_l ; x_r = X@W_r + b_r, fp16 out, packed f32x2 FMA.
// X pre-packed (replicated) into u64 smem once; inner loop is pure FMA2.
// ---------------------------------------------------------------------------
__global__ __launch_bounds__(256) void proj_kernel(
    const float* __restrict__ X,
    const float* __restrict__ Wl, const float* __restrict__ bl,
    const float* __restrict__ Wr, const float* __restrict__ br)
{
    __shared__ unsigned long long sx2[128 * IN_DIM];  // 16 KB
    const int c0 = threadIdx.x * 2;
    unsigned long long wl[IN_DIM], wr[IN_DIM];
#pragma unroll
    for (int k = 0; k < IN_DIM; k++) {
        wl[k] = pack2(Wl[k * HC + c0], Wl[k * HC + c0 + 1]);
        wr[k] = pack2(Wr[k * HC + c0], Wr[k * HC + c0 + 1]);
    }
    const unsigned long long bl2 = pack2(bl[c0], bl[c0 + 1]);
    const unsigned long long br2 = pack2(br[c0], br[c0 + 1]);

    const int n0 = blockIdx.x * 128;
    const int nmax = min(128, N_NODES - n0);

    for (int i = threadIdx.x; i < nmax * IN_DIM; i += blockDim.x) {
        const float v = X[(size_t)n0 * IN_DIM + i];
        sx2[i] = pack2(v, v);
    }
    __syncthreads();

    for (int n = 0; n < nmax; n++) {
        unsigned long long al = bl2, ar = br2;
#pragma unroll
        for (int k = 0; k < IN_DIM; k++) {
            const unsigned long long x2 = sx2[n * IN_DIM + k];
            ffma2(al, x2, wl[k]);
            ffma2(ar, x2, wr[k]);
        }
        float l0, l1, r0, r1;
        unpack2(al, l0, l1);
        unpack2(ar, r0, r1);
        const size_t o = ((size_t)(n0 + n) * HC + c0) >> 1;
        ((__half2*)g_xl)[o] = __floats2half2_rn(l0, l1);
        ((__half2*)g_xr)[o] = __floats2half2_rn(r0, r1);
    }
}

// ---------------------------------------------------------------------------
// CSR build: histogram -> single-block scan -> fill
// ---------------------------------------------------------------------------
__global__ __launch_bounds__(256) void hist_kernel(const int* __restrict__ idx)
{
    const int e = blockIdx.x * blockDim.x + threadIdx.x;
    if (e < N_EDGES) atomicAdd(&g_counts[idx[N_EDGES + e]], 1);
}

__global__ __launch_bounds__(1024) void scan_kernel()
{
    __shared__ int sp[1024];
    const int t = threadIdx.x;
    const int CH = (N_NODES + 1023) / 1024;
    const int base = t * CH;
    const int lim = min(CH, N_NODES - base);

    int sum = 0;
    for (int i = 0; i < lim; i++) sum += g_counts[base + i];
    sp[t] = sum;
    __syncthreads();
    for (int off = 1; off < 1024; off <<= 1) {
        int v = (t >= off) ? sp[t - off] : 0;
        __syncthreads();
        sp[t] += v;
        __syncthreads();
    }
    int run = (t > 0) ? sp[t - 1] : 0;
    for (int i = 0; i < lim; i++) {
        g_row[base + i] = run;
        g_cursor[base + i] = run;
        run += g_counts[base + i];
    }
    if (t == 0) g_row[N_NODES] = N_EDGES;
}

__global__ __launch_bounds__(256) void fill_kernel(const int* __restrict__ idx)
{
    const int e = blockIdx.x * blockDim.x + threadIdx.x;
    if (e >= N_EDGES) return;
    const int dst = idx[N_EDGES + e];
    const int pos = atomicAdd(&g_cursor[dst], 1);
    g_srcs[pos] = idx[e];
    g_dsts[pos] = dst;
}

// ---------------------------------------------------------------------------
// K2: edge-centric scores in CSR order (consecutive slots share dst -> L1/L2
// reuse of x_r row). One warp per CSR slot. Writes ex4 to g_ex[slot].
// x_l loads hinted evict_last (keep resident for the aggregate pass);
// x_r loads evict_first (streaming; short-term reuse lives in L1).
// No max-subtraction: scores are O(1), exp safe in fp32, softmax ratio exact.
// ---------------------------------------------------------------------------
__global__ __launch_bounds__(256) void score_kernel(const float* __restrict__ att)
{
    const int j = blockIdx.x * 8 + (threadIdx.x >> 5);
    if (j >= N_EDGES) return;
    const int lane = threadIdx.x & 31;
    const int src = g_srcs[j];
    const int dst = g_dsts[j];

    const unsigned long long pol_l = policy_evict_last();
    const unsigned long long pol_f = policy_evict_first();

    const uint2* __restrict__ xls = ((const uint2*)g_xl) + (size_t)src * 128;
    const uint2* __restrict__ xrs = ((const uint2*)g_xr) + (size_t)dst * 128;
    const float4* __restrict__ att4 = (const float4*)att;

    float eh[HEADS];
#pragma unroll
    for (int h = 0; h < HEADS; h++) {
        const uint2 ap = ld_hint_u2(&xls[h * 32 + lane], pol_l);
        const uint2 bp = ld_hint_u2(&xrs[h * 32 + lane], pol_f);
        const float2 a0 = __half22float2(*(const __half2*)&ap.x);
        const float2 a1 = __half22float2(*(const __half2*)&ap.y);
        const float2 b0 = __half22float2(*(const __half2*)&bp.x);
        const float2 b1 = __half22float2(*(const __half2*)&bp.y);

        const float4 w = __ldg(&att4[h * 32 + lane]);
        float s = lrelu(a0.x + b0.x) * w.x;
        s = fmaf(lrelu(a0.y + b0.y), w.y, s);
        s = fmaf(lrelu(a1.x + b1.x), w.z, s);
        s = fmaf(lrelu(a1.y + b1.y), w.w, s);
#pragma unroll
        for (int off = 16; off > 0; off >>= 1)
            s += __shfl_xor_sync(0xffffffffu, s, off);
        eh[h] = s;
    }

    if (lane == 0) {
        float4 ex;
        ex.x = __expf(eh[0]);
        ex.y = __expf(eh[1]);
        ex.z = __expf(eh[2]);
        ex.w = __expf(eh[3]);
        ((float4*)g_ex)[j] = ex;
    }
}

// ---------------------------------------------------------------------------
// K3: node-centric aggregate. One warp per node; loop over CSR slots:
// uniform ex4 + vector x_l gather (evict_last) + FMA. Registers only;
// single streaming write with 1/den and bias fused. No atomics, no memset
// of out, no finalize pass.
// ---------------------------------------------------------------------------
__global__ __launch_bounds__(256) void aggregate_kernel(
    const float* __restrict__ bias, float* __restrict__ out)
{
    const int node = blockIdx.x * 8 + (threadIdx.x >> 5);
    if (node >= N_NODES) return;
    const int lane = threadIdx.x & 31;

    const unsigned long long pol_l = policy_evict_last();

    const int eb = g_row[node];
    const int ee = g_row[node + 1];

    float4 acc[HEADS];
#pragma unroll
    for (int h = 0; h < HEADS; h++) acc[h] = make_float4(0.f, 0.f, 0.f, 0.f);
    float4 den = make_float4(0.f, 0.f, 0.f, 0.f);

    for (int j = eb; j < ee; j++) {
        const int src = g_srcs[j];                       // lane-uniform
        const float4 ex = __ldg(&((const float4*)g_ex)[j]);
        const uint2* __restrict__ xlp = ((const uint2*)g_xl) + (size_t)src * 128;
#pragma unroll
        for (int h = 0; h < HEADS; h++) {
            const uint2 p = ld_hint_u2(&xlp[h * 32 + lane], pol_l);
            const float2 f0 = __half22float2(*(const __half2*)&p.x);
            const float2 f1 = __half22float2(*(const __half2*)&p.y);
            const float s = (h == 0) ? ex.x : (h == 1) ? ex.y : (h == 2) ? ex.z : ex.w;
            acc[h].x = fmaf(s, f0.x, acc[h].x);
            acc[h].y = fmaf(s, f0.y, acc[h].y);
            acc[h].z = fmaf(s, f1.x, acc[h].z);
            acc[h].w = fmaf(s, f1.y, acc[h].w);
        }
        den.x += ex.x; den.y += ex.y; den.z += ex.z; den.w += ex.w;
    }

    const float invd[HEADS] = {
        den.x > 0.f ? 1.0f / den.x : 0.f,
        den.y > 0.f ? 1.0f / den.y : 0.f,
        den.z > 0.f ? 1.0f / den.z : 0.f,
        den.w > 0.f ? 1.0f / den.w : 0.f
    };

    float4* op = ((float4*)out) + (size_t)node * (HC / 4);
#pragma unroll
    for (int h = 0; h < HEADS; h++) {
        const float4 b = __ldg(&((const float4*)bias)[h * 32 + lane]);
        float4 o;
        o.x = fmaf(acc[h].x, invd[h], b.x);
        o.y = fmaf(acc[h].y, invd[h], b.y);
        o.z = fmaf(acc[h].z, invd[h], b.z);
        o.w = fmaf(acc[h].w, invd[h], b.w);
        st_stream_f4(&op[h * 32 + lane], o);
    }
}

// ---------------------------------------------------------------------------
extern "C" void kernel_launch(void* const* d_in, const int* in_sizes, int n_in,
                              void* d_out, int out_size)
{
    const float* X    = (const float*)d_in[0];  // [N, 16]
    const int*   idx  = (const int*)  d_in[1];  // [2, E]
    const float* Wl   = (const float*)d_in[2];  // [16, 512]
    const float* bl   = (const float*)d_in[3];  // [512]
    const float* Wr   = (const float*)d_in[4];  // [16, 512]
    const float* br   = (const float*)d_in[5];  // [512]
    const float* att  = (const float*)d_in[6];  // [4, 128]
    const float* bias = (const float*)d_in[7];  // [512]
    float* out = (float*)d_out;                 // [N, 512]

    void* counts_ptr = nullptr;
    cudaGetSymbolAddress(&counts_ptr, g_counts);
    cudaMemsetAsync(counts_ptr, 0, N_NODES * sizeof(int), 0);

    proj_kernel<<<(N_NODES + 127) / 128, 256>>>(X, Wl, bl, Wr, br);
    hist_kernel<<<(N_EDGES + 255) / 256, 256>>>(idx);
    scan_kernel<<<1, 1024>>>();
    fill_kernel<<<(N_EDGES + 255) / 256, 256>>>(idx);
    score_kernel<<<(N_EDGES + 7) / 8, 256>>>(att);
    aggregate_kernel<<<(N_NODES + 7) / 8, 256>>>(bias, out);
}